// round 13
// baseline (speedup 1.0000x reference)
#include <cuda_runtime.h>
#include <cuda_bf16.h>
#include <cstdint>
#include <math.h>

#define MDIM 64
#define NDIM 4096
#define BN   64
#define NST  3
#define KSPL 1024
#define NCH  (KSPL / 64)     // 16 chunks per K-split
#define NSPLIT (NDIM / KSPL) // 4
#define KCHEB 14

#define TILEP 16384                    // 64x64 bf16 hi+lo pair (8192 + 8192)
#define STAGE_BYTES 32768              // A pair (16KB) + B fp32 (16KB)
#define TX_BYTES 32768
#define GEMM_SMEM (128 + NST * STAGE_BYTES + 16384)   // 114816

#define GST 72
#define TST 40

// Scratch (allocation-free rule: __device__ globals)
__device__ float g_Gt[MDIM * MDIM];
__device__ float g_Y [MDIM * NDIM];
__device__ __align__(128) char g_Xt[64 * TILEP];   // X tiles (bf16 pair, swizzled)
__device__ __align__(128) char g_Ztt[64 * TILEP];  // Z~ tiles (bf16 pair, swizzled)

// ---------------------------------------------------------------------------
// PTX helpers
// ---------------------------------------------------------------------------
__device__ __forceinline__ uint32_t sptr(const void* p) {
    return (uint32_t)__cvta_generic_to_shared(p);
}
__device__ __forceinline__ void ldsm4(uint32_t r[4], uint32_t addr) {
    asm volatile("ldmatrix.sync.aligned.m8n8.x4.shared.b16 {%0,%1,%2,%3}, [%4];"
                 : "=r"(r[0]), "=r"(r[1]), "=r"(r[2]), "=r"(r[3]) : "r"(addr));
}
__device__ __forceinline__ void ldsm4t(uint32_t r[4], uint32_t addr) {
    asm volatile("ldmatrix.sync.aligned.m8n8.x4.trans.shared.b16 {%0,%1,%2,%3}, [%4];"
                 : "=r"(r[0]), "=r"(r[1]), "=r"(r[2]), "=r"(r[3]) : "r"(addr));
}
__device__ __forceinline__ void mma16816(float d[4], const uint32_t a[4],
                                         uint32_t b0, uint32_t b1) {
    asm volatile("mma.sync.aligned.m16n8k16.row.col.f32.bf16.bf16.f32 "
                 "{%0,%1,%2,%3}, {%4,%5,%6,%7}, {%8,%9}, {%0,%1,%2,%3};"
                 : "+f"(d[0]), "+f"(d[1]), "+f"(d[2]), "+f"(d[3])
                 : "r"(a[0]), "r"(a[1]), "r"(a[2]), "r"(a[3]),
                   "r"(b0), "r"(b1));
}
__device__ __forceinline__ void bulk_ld(uint32_t dst, const void* src,
                                        uint32_t bytes, uint32_t mbar) {
    asm volatile("cp.async.bulk.shared::cluster.global.mbarrier::complete_tx::bytes "
                 "[%0], [%1], %2, [%3];"
                 :: "r"(dst), "l"(src), "r"(bytes), "r"(mbar) : "memory");
}
__device__ __forceinline__ void mbar_init(uint32_t a, uint32_t cnt) {
    asm volatile("mbarrier.init.shared.b64 [%0], %1;" :: "r"(a), "r"(cnt) : "memory");
}
__device__ __forceinline__ void mbar_expect_tx(uint32_t a, uint32_t bytes) {
    asm volatile("mbarrier.arrive.expect_tx.shared.b64 _, [%0], %1;"
                 :: "r"(a), "r"(bytes) : "memory");
}
__device__ __forceinline__ void mbar_wait(uint32_t a, uint32_t parity) {
    asm volatile(
        "{\n\t.reg .pred P;\n\t"
        "WAIT_%=:\n\t"
        "mbarrier.try_wait.parity.acquire.cta.shared::cta.b64 P, [%0], %1, 0x989680;\n\t"
        "@P bra.uni DONE_%=;\n\t"
        "bra.uni WAIT_%=;\n\t"
        "DONE_%=:\n\t}"
        :: "r"(a), "r"(parity) : "memory");
}
__device__ __forceinline__ void fence_async_init() {
    asm volatile("fence.proxy.async.shared::cta;" ::: "memory");
}

__device__ __forceinline__ void bf16split(float x, __nv_bfloat16& h, __nv_bfloat16& l) {
    h = __float2bfloat16(x);
    l = __float2bfloat16(x - __bfloat162float(h));
}
__device__ __forceinline__ void split2pack(float a, float b, uint32_t& hp, uint32_t& lp) {
    __nv_bfloat16 ha, la, hb, lb;
    bf16split(a, ha, la);
    bf16split(b, hb, lb);
    __nv_bfloat162 h; h.x = ha; h.y = hb;
    __nv_bfloat162 l; l.x = la; l.y = lb;
    hp = *(uint32_t*)&h;
    lp = *(uint32_t*)&l;
}

// ---------------------------------------------------------------------------
// Convert X into tiled, pre-swizzled bf16 hi/lo tile pairs (tiny: 1MB read)
// ---------------------------------------------------------------------------
__global__ __launch_bounds__(256) void conv_x_kernel(const float4* __restrict__ X) {
    uint32_t gid = blockIdx.x * 256 + threadIdx.x;     // 64*4096/4 = 65536 total
    float4 v = X[gid];
    uint32_t r = gid >> 10;
    uint32_t c = (gid & 1023) * 4;
    char* base = g_Xt + (size_t)(c >> 6) * TILEP;
    const uint32_t i = r & 63, j = c & 63;
    const uint32_t sw = (i * 128 + j * 2) ^ ((i & 7) << 4);
    uint32_t h0, l0, h1, l1;
    split2pack(v.x, v.y, h0, l0);
    split2pack(v.z, v.w, h1, l1);
    *(uint2*)(base + sw)        = make_uint2(h0, h1);
    *(uint2*)(base + 8192 + sw) = make_uint2(l0, l1);
}

// ---------------------------------------------------------------------------
// Zero-init Y and Z (outputs accumulated via atomicAdd each replay)
// ---------------------------------------------------------------------------
__global__ __launch_bounds__(256) void zero_kernel(float* __restrict__ a,
                                                   float* __restrict__ b) {
    int i = blockIdx.x * 256 + threadIdx.x;
    a[i] = 0.0f;
    b[i] = 0.0f;
}

// ---------------------------------------------------------------------------
// G~ = 2 * (F^T F) / (||F^T F||_F + 1e-12) - I
// ---------------------------------------------------------------------------
__global__ __launch_bounds__(256) void prep_kernel(const float* __restrict__ F) {
    __shared__ float Fs[MDIM][MDIM + 1];
    __shared__ float FFs[MDIM][MDIM + 4];
    __shared__ float red[8];
    __shared__ float s_inv;

    int t = threadIdx.x;
    for (int o = t; o < MDIM * MDIM; o += 256)
        Fs[o >> 6][o & 63] = F[o];
    __syncthreads();

    int i  = t >> 2;
    int j0 = (t & 3) * 16;
    float acc[16];
#pragma unroll
    for (int u = 0; u < 16; u++) acc[u] = 0.0f;
    for (int k = 0; k < MDIM; k++) {
        float a = Fs[k][i];
#pragma unroll
        for (int u = 0; u < 16; u++) acc[u] = fmaf(a, Fs[k][j0 + u], acc[u]);
    }
    float ss = 0.0f;
#pragma unroll
    for (int u = 0; u < 16; u++) {
        FFs[i][j0 + u] = acc[u];
        ss = fmaf(acc[u], acc[u], ss);
    }
#pragma unroll
    for (int off = 16; off > 0; off >>= 1)
        ss += __shfl_xor_sync(0xffffffffu, ss, off);
    if ((t & 31) == 0) red[t >> 5] = ss;
    __syncthreads();
    if (t == 0) {
        float tot = 0.0f;
        for (int w = 0; w < 8; w++) tot += red[w];
        s_inv = 2.0f / (sqrtf(tot) + 1e-12f);
    }
    __syncthreads();
    float inv = s_inv;
#pragma unroll
    for (int u = 0; u < 16; u++) {
        int j = j0 + u;
        g_Gt[i * MDIM + j] = FFs[i][j] * inv - (i == j ? 1.0f : 0.0f);
    }
}

// ---------------------------------------------------------------------------
// TMA-staged bf16 tensor GEMM. A tiles are pre-converted bf16 pairs (one 16KB
// bulk). B tiles are loaded as RAW fp32 straight from Q (64 x 256B row bulks)
// and split to bf16 hi/lo in-kernel into a single shared pair buffer.
// No empty mbarriers: the two per-chunk __syncthreads serialize stage reuse.
// TRANSB=0: B tile rows = k (Q[kbase.., jg..]);  TRANSB=1: rows = n (Q[jg.., kbase..])
// ---------------------------------------------------------------------------
template <int TRANSB>
__global__ __launch_bounds__(256) void gemm_bf(const char* __restrict__ At,
                                               const float* __restrict__ Q,
                                               float* __restrict__ C) {
    extern __shared__ __align__(128) char sm[];
    const uint32_t smb = sptr(sm);

    const int t    = threadIdx.x;
    const int lane = t & 31;
    const int warp = t >> 5;
    const int jb   = blockIdx.x;
    const int jg   = jb * BN;
    const int kb0  = blockIdx.y * (KSPL / 64);
    const int mw   = (warp & 3) * 16;
    const int nw   = (warp >> 2) * 32;
    const int lr   = lane & 15;
    const int g8   = (lane >> 4) * 8;

    if (t == 0) {
#pragma unroll
        for (int s = 0; s < NST; s++)
            mbar_init(smb + s * 16, 1);     // full barriers only (thread0 expect_tx)
        fence_async_init();
    }
    __syncthreads();

    // A source: tile pairs, contiguous 16KB each
    const char* srcA = At + (size_t)kb0 * TILEP;
    // B source: this thread's row (threads 0..63 participate)
    const float* srcB;
    long dB;
    if (TRANSB) { srcB = Q + (size_t)(jg + t) * NDIM + (size_t)kb0 * 64; dB = 64 * 4; }
    else        { srcB = Q + ((size_t)kb0 * 64 + t) * NDIM + jg;         dB = (long)64 * NDIM * 4; }

    const uint32_t stage0 = smb + 128;
    const uint32_t Bpair  = smb + 128 + NST * STAGE_BYTES;   // shared 16KB pair buffer

    // per-thread swizzled ldsm offsets (loop-invariant)
    const uint32_t xorv = (uint32_t)(lane & 7) << 4;
    uint32_t aoffs[4];
#pragma unroll
    for (int ks = 0; ks < 4; ks++)
        aoffs[ks] = (uint32_t)(mw + lr) * 128 + (((uint32_t)(ks * 32 + g8 * 2)) ^ xorv);
    uint32_t boffs[4][2];
#pragma unroll
    for (int ks = 0; ks < 4; ks++)
#pragma unroll
        for (int half = 0; half < 2; half++) {
            if (TRANSB == 0)
                boffs[ks][half] = (uint32_t)(ks * 16 + lr) * 128 +
                                  (((uint32_t)((nw + half * 16 + g8) * 2)) ^ xorv);
            else
                boffs[ks][half] = (uint32_t)(nw + half * 16 + lr) * 128 +
                                  (((uint32_t)(ks * 32 + g8 * 2)) ^ xorv);
        }

    // convert-phase mapping: thread t handles 4 float4 at idx = t + 256*q
    const uint32_t cv_row0 = (uint32_t)(t >> 4);         // +16q
    const uint32_t cv_col  = (uint32_t)(t & 15) * 4;

    float acc[4][4];
#pragma unroll
    for (int nt = 0; nt < 4; nt++)
#pragma unroll
        for (int u = 0; u < 4; u++) acc[nt][u] = 0.0f;

    // prologue: issue chunks 0 and 1 (stages 0,1)
#pragma unroll
    for (int cn = 0; cn < NST - 1; cn++) {
        const uint32_t full = smb + cn * 16;
        if (t == 0) {
            mbar_expect_tx(full, TX_BYTES);
            bulk_ld(stage0 + cn * STAGE_BYTES, srcA + (long)cn * TILEP, TILEP, full);
        }
        if (t < 64)
            bulk_ld(stage0 + cn * STAGE_BYTES + TILEP + t * 256,
                    (const char*)srcB + (long)cn * dB, 256, full);
    }

#pragma unroll
    for (int cb = 0; cb < NCH; cb += NST) {
        const int q    = cb / NST;
        const int cpar = q & 1;
#pragma unroll
        for (int s = 0; s < NST; s++) {
            const int cc = cb + s;
            if (cc >= NCH) break;
            const int cn = cc + NST - 1;              // chunk to issue
            const int istage = (s + NST - 1) % NST;

            // wait chunk cc's stage full, then block-sync (prev chunk fully consumed)
            mbar_wait(smb + s * 16, cpar);
            __syncthreads();

            if (cn < NCH) {
                const uint32_t full = smb + istage * 16;
                if (t == 0) {
                    mbar_expect_tx(full, TX_BYTES);
                    bulk_ld(stage0 + istage * STAGE_BYTES, srcA + (long)cn * TILEP, TILEP, full);
                }
                if (t < 64)
                    bulk_ld(stage0 + istage * STAGE_BYTES + TILEP + t * 256,
                            (const char*)srcB + (long)cn * dB, 256, full);
            }

            // convert fp32 B tile of stage s -> Bpair (hi at 0, lo at 8192)
            {
                const uint32_t Bf = stage0 + s * STAGE_BYTES + TILEP;
#pragma unroll
                for (int qq = 0; qq < 4; qq++) {
                    float4 v;
                    asm volatile("ld.shared.v4.f32 {%0,%1,%2,%3}, [%4];"
                                 : "=f"(v.x), "=f"(v.y), "=f"(v.z), "=f"(v.w)
                                 : "r"(Bf + (uint32_t)(t + 256 * qq) * 16));
                    const uint32_t row = cv_row0 + 16 * qq;
                    const uint32_t sw = (row * 128 + cv_col * 2) ^ ((row & 7) << 4);
                    uint32_t h0, l0, h1, l1;
                    split2pack(v.x, v.y, h0, l0);
                    split2pack(v.z, v.w, h1, l1);
                    asm volatile("st.shared.v2.b32 [%0], {%1,%2};"
                                 :: "r"(Bpair + sw), "r"(h0), "r"(h1));
                    asm volatile("st.shared.v2.b32 [%0], {%1,%2};"
                                 :: "r"(Bpair + 8192 + sw), "r"(l0), "r"(l1));
                }
            }
            __syncthreads();

            const uint32_t Ah = stage0 + s * STAGE_BYTES;
            const uint32_t Al = Ah + 8192;
            const uint32_t Bh = Bpair;
            const uint32_t Bl = Bpair + 8192;

#pragma unroll
            for (int ks = 0; ks < 4; ks++) {
                uint32_t ah[4], al[4];
                ldsm4(ah, Ah + aoffs[ks]);
                ldsm4(al, Al + aoffs[ks]);
#pragma unroll
                for (int half = 0; half < 2; half++) {
                    uint32_t bh[4], bl[4];
                    if (TRANSB == 0) {
                        ldsm4t(bh, Bh + boffs[ks][half]);
                        ldsm4t(bl, Bl + boffs[ks][half]);
                        mma16816(acc[half * 2],     ah, bh[0], bh[1]);
                        mma16816(acc[half * 2],     ah, bl[0], bl[1]);
                        mma16816(acc[half * 2],     al, bh[0], bh[1]);
                        mma16816(acc[half * 2 + 1], ah, bh[2], bh[3]);
                        mma16816(acc[half * 2 + 1], ah, bl[2], bl[3]);
                        mma16816(acc[half * 2 + 1], al, bh[2], bh[3]);
                    } else {
                        ldsm4(bh, Bh + boffs[ks][half]);
                        ldsm4(bl, Bl + boffs[ks][half]);
                        mma16816(acc[half * 2],     ah, bh[0], bh[2]);
                        mma16816(acc[half * 2],     ah, bl[0], bl[2]);
                        mma16816(acc[half * 2],     al, bh[0], bh[2]);
                        mma16816(acc[half * 2 + 1], ah, bh[1], bh[3]);
                        mma16816(acc[half * 2 + 1], ah, bl[1], bl[3]);
                        mma16816(acc[half * 2 + 1], al, bh[1], bh[3]);
                    }
                }
            }
        }
    }

    const int row = mw + (lane >> 2);
#pragma unroll
    for (int nt = 0; nt < 4; nt++) {
        const int col = jg + nw + (nt >> 1) * 16 + (nt & 1) * 8 + (lane & 3) * 2;
        atomicAdd(&C[(size_t)row * NDIM + col],           acc[nt][0]);
        atomicAdd(&C[(size_t)row * NDIM + col + 1],       acc[nt][1]);
        atomicAdd(&C[(size_t)(row + 8) * NDIM + col],     acc[nt][2]);
        atomicAdd(&C[(size_t)(row + 8) * NDIM + col + 1], acc[nt][3]);
    }
}

// ---------------------------------------------------------------------------
// Tensor-core Chebyshev (unchanged). Output into tiled/pre-swizzled g_Ztt.
// ---------------------------------------------------------------------------
__global__ __launch_bounds__(256) void cheb_tc(const float* __restrict__ lamS,
                                               const float* __restrict__ gammap) {
    extern __shared__ __align__(16) __nv_bfloat16 cs[];
    __nv_bfloat16* Gh = cs;
    __nv_bfloat16* Gl = cs + 64 * GST;
    __nv_bfloat16* Tbh = cs + 2 * 64 * GST;
    __nv_bfloat16* Tbl = Tbh + 3 * 64 * TST;
    __shared__ float sh_base[32];
    __shared__ float sh_r[32];

    const int t    = threadIdx.x;
    const int lane = t & 31;
    const int warp = t >> 5;
    const int jg   = blockIdx.x * 32;
    const int mw   = (warp & 3) * 16;
    const int nw   = (warp >> 2) * 16;
    const int lr   = lane & 15;
    const int g8   = (lane >> 4) * 8;

    for (int o = t; o < MDIM * MDIM; o += 256) {
        int r = o >> 6, c = o & 63;
        __nv_bfloat16 h, l;
        bf16split(g_Gt[o], h, l);
        Gh[r * GST + c] = h;
        Gl[r * GST + c] = l;
    }
    for (int o = t; o < MDIM * 32; o += 256) {
        int r = o >> 5, c = o & 31;
        __nv_bfloat16 h, l;
        bf16split(g_Y[(size_t)r * NDIM + jg + c], h, l);
        Tbh[r * TST + c] = h;
        Tbl[r * TST + c] = l;
    }
    if (t < 32) {
        float gam = gammap[0];
        float a = gam * lamS[jg + t];
        float base, r;
        if (fabsf(a) < 1e-7f) {
            base = 1.0f; r = 0.0f;
        } else {
            float b  = 2.0f / a - 1.0f;
            float ab = fabsf(b);
            float s  = sqrtf(fmaf(ab, ab, -1.0f));
            float q  = 1.0f / (ab + s);
            float sg = (a > 0.0f) ? 1.0f : -1.0f;
            r    = sg * q;
            base = (2.0f / a) * sg * 2.0f * q / (1.0f - q * q);
        }
        sh_base[t] = base;
        sh_r[t]    = r;
    }
    __syncthreads();

    uint32_t gh[4][4], gl[4][4];
#pragma unroll
    for (int ks = 0; ks < 4; ks++) {
        ldsm4(gh[ks], sptr(Gh + (mw + lr) * GST + ks * 16 + g8));
        ldsm4(gl[ks], sptr(Gl + (mw + lr) * GST + ks * 16 + g8));
    }

    const int row0 = mw + (lane >> 2);
    float basev[2][2], rv[2][2], pv[2][2];
#pragma unroll
    for (int nt = 0; nt < 2; nt++) {
        int c0 = nw + nt * 8 + 2 * (lane & 3);
        basev[nt][0] = sh_base[c0];     basev[nt][1] = sh_base[c0 + 1];
        rv[nt][0]    = sh_r[c0];        rv[nt][1]    = sh_r[c0 + 1];
        pv[nt][0] = 2.0f * basev[nt][0] * rv[nt][0];
        pv[nt][1] = 2.0f * basev[nt][1] * rv[nt][1];
    }

    float acc[2][4], prev[2][4], tp[2][4];
#pragma unroll
    for (int nt = 0; nt < 2; nt++) {
        int c0 = nw + nt * 8 + 2 * (lane & 3);
        float2 y0 = *(const float2*)&g_Y[(size_t)row0 * NDIM + jg + c0];
        float2 y1 = *(const float2*)&g_Y[(size_t)(row0 + 8) * NDIM + jg + c0];
        prev[nt][0] = y0.x; prev[nt][1] = y0.y; prev[nt][2] = y1.x; prev[nt][3] = y1.y;
        acc[nt][0] = basev[nt][0] * y0.x;
        acc[nt][1] = basev[nt][1] * y0.y;
        acc[nt][2] = basev[nt][0] * y1.x;
        acc[nt][3] = basev[nt][1] * y1.y;
        tp[nt][0] = tp[nt][1] = tp[nt][2] = tp[nt][3] = 0.0f;
    }

    for (int k = 1; k < KCHEB; k++) {
        __syncthreads();
        const __nv_bfloat16* Th = Tbh + ((k - 1) % 3) * (64 * TST);
        const __nv_bfloat16* Tl = Tbl + ((k - 1) % 3) * (64 * TST);
        float u[2][4];
#pragma unroll
        for (int nt = 0; nt < 2; nt++)
#pragma unroll
            for (int i = 0; i < 4; i++) u[nt][i] = 0.0f;
#pragma unroll
        for (int ks = 0; ks < 4; ks++) {
            uint32_t th[4], tl[4];
            ldsm4t(th, sptr(Th + (ks * 16 + lr) * TST + nw + g8));
            ldsm4t(tl, sptr(Tl + (ks * 16 + lr) * TST + nw + g8));
            mma16816(u[0], gh[ks], th[0], th[1]);
            mma16816(u[0], gh[ks], tl[0], tl[1]);
            mma16816(u[0], gl[ks], th[0], th[1]);
            mma16816(u[1], gh[ks], th[2], th[3]);
            mma16816(u[1], gh[ks], tl[2], tl[3]);
            mma16816(u[1], gl[ks], th[2], th[3]);
        }
        float tn[2][4];
#pragma unroll
        for (int nt = 0; nt < 2; nt++)
#pragma unroll
            for (int i = 0; i < 4; i++)
                tn[nt][i] = (k == 1) ? u[nt][i] : fmaf(2.0f, u[nt][i], -tp[nt][i]);
#pragma unroll
        for (int nt = 0; nt < 2; nt++) {
            acc[nt][0] = fmaf(pv[nt][0], tn[nt][0], acc[nt][0]);
            acc[nt][1] = fmaf(pv[nt][1], tn[nt][1], acc[nt][1]);
            acc[nt][2] = fmaf(pv[nt][0], tn[nt][2], acc[nt][2]);
            acc[nt][3] = fmaf(pv[nt][1], tn[nt][3], acc[nt][3]);
            pv[nt][0] *= rv[nt][0];
            pv[nt][1] *= rv[nt][1];
        }
        if (k < KCHEB - 1) {
            __nv_bfloat16* Wh = Tbh + (k % 3) * (64 * TST);
            __nv_bfloat16* Wl = Tbl + (k % 3) * (64 * TST);
#pragma unroll
            for (int nt = 0; nt < 2; nt++) {
                int c0 = nw + nt * 8 + 2 * (lane & 3);
                uint32_t hp, lp;
                split2pack(tn[nt][0], tn[nt][1], hp, lp);
                *(uint32_t*)(Wh + row0 * TST + c0) = hp;
                *(uint32_t*)(Wl + row0 * TST + c0) = lp;
                split2pack(tn[nt][2], tn[nt][3], hp, lp);
                *(uint32_t*)(Wh + (row0 + 8) * TST + c0) = hp;
                *(uint32_t*)(Wl + (row0 + 8) * TST + c0) = lp;
            }
        }
#pragma unroll
        for (int nt = 0; nt < 2; nt++)
#pragma unroll
            for (int i = 0; i < 4; i++) {
                tp[nt][i]   = prev[nt][i];
                prev[nt][i] = tn[nt][i];
            }
    }

    {
        char* Zt = g_Ztt + (size_t)(jg >> 6) * TILEP;
        const uint32_t jo = jg & 63;
#pragma unroll
        for (int nt = 0; nt < 2; nt++) {
            const uint32_t c0 = nw + nt * 8 + 2 * (lane & 3);
            uint32_t hp, lp;
            split2pack(acc[nt][0], acc[nt][1], hp, lp);
            uint32_t o0 = (uint32_t)row0 * 128 + (((jo + c0) * 2) ^ (((uint32_t)row0 & 7) << 4));
            *(uint32_t*)(Zt + o0)        = hp;
            *(uint32_t*)(Zt + 8192 + o0) = lp;
            split2pack(acc[nt][2], acc[nt][3], hp, lp);
            uint32_t o1 = (uint32_t)(row0 + 8) * 128 + (((jo + c0) * 2) ^ (((uint32_t)row0 & 7) << 4));
            *(uint32_t*)(Zt + o1)        = hp;
            *(uint32_t*)(Zt + 8192 + o1) = lp;
        }
    }
}

#define CHEB_SMEM ((2 * 64 * GST + 6 * 64 * TST) * 2)

// ---------------------------------------------------------------------------
extern "C" void kernel_launch(void* const* d_in, const int* in_sizes, int n_in,
                              void* d_out, int out_size) {
    const float* X    = (const float*)d_in[0];   // (64, 4096)
    const float* F    = (const float*)d_in[1];   // (64, 64)
    const float* Q_S  = (const float*)d_in[2];   // (4096, 4096)
    const float* lamS = (const float*)d_in[3];   // (4096,)
    const float* gam  = (const float*)d_in[4];   // scalar
    float* Z = (float*)d_out;                    // (64, 4096)

    float* Y;
    char *Xt, *Ztt;
    cudaGetSymbolAddress((void**)&Y,   g_Y);
    cudaGetSymbolAddress((void**)&Xt,  g_Xt);
    cudaGetSymbolAddress((void**)&Ztt, g_Ztt);

    static bool attr_set = false;
    if (!attr_set) {
        cudaFuncSetAttribute(gemm_bf<0>, cudaFuncAttributeMaxDynamicSharedMemorySize, GEMM_SMEM);
        cudaFuncSetAttribute(gemm_bf<1>, cudaFuncAttributeMaxDynamicSharedMemorySize, GEMM_SMEM);
        cudaFuncSetAttribute(cheb_tc,    cudaFuncAttributeMaxDynamicSharedMemorySize, CHEB_SMEM);
        attr_set = true;
    }

    dim3 ggrid(NDIM / BN, NSPLIT);

    conv_x_kernel<<<(MDIM * NDIM / 4) / 256, 256>>>((const float4*)X);
    zero_kernel<<<(MDIM * NDIM) / 256, 256>>>(Y, Z);
    prep_kernel<<<1, 256>>>(F);
    gemm_bf<0><<<ggrid, 256, GEMM_SMEM>>>(Xt, Q_S, Y);    // Y += X @ Q_S
    cheb_tc<<<NDIM / 32, 256, CHEB_SMEM>>>(lamS, gam);    // Ztt = f(G) Y (tiled)
    gemm_bf<1><<<ggrid, 256, GEMM_SMEM>>>(Ztt, Q_S, Z);   // Z += Z~ @ Q_S^T
}

// round 14
// speedup vs baseline: 1.0928x; 1.0928x over previous
#include <cuda_runtime.h>
#include <cuda_bf16.h>
#include <cstdint>
#include <math.h>

#define MDIM 64
#define NDIM 4096
#define BN   64
#define NST  3
#define KSPL 1024
#define NCH  (KSPL / 64)     // 16 chunks per K-split
#define NSPLIT (NDIM / KSPL) // 4
#define KCHEB 14

#define TILEP 16384                          // 64x64 bf16 hi+lo pair
#define ATILE 16384
#define ATX   16384
#define GEMM_SMEM (128 + NST * ATILE + 2 * TILEP)   // 82048

#define GST 72
#define TST 40

// Scratch (allocation-free rule: __device__ globals)
__device__ float g_Gt[MDIM * MDIM];
__device__ float g_Y [MDIM * NDIM];
__device__ __align__(128) char g_Xt[64 * TILEP];   // X tiles (bf16 pair, swizzled)
__device__ __align__(128) char g_Ztt[64 * TILEP];  // Z~ tiles (bf16 pair, swizzled)

// ---------------------------------------------------------------------------
// PTX helpers
// ---------------------------------------------------------------------------
__device__ __forceinline__ uint32_t sptr(const void* p) {
    return (uint32_t)__cvta_generic_to_shared(p);
}
__device__ __forceinline__ void ldsm4(uint32_t r[4], uint32_t addr) {
    asm volatile("ldmatrix.sync.aligned.m8n8.x4.shared.b16 {%0,%1,%2,%3}, [%4];"
                 : "=r"(r[0]), "=r"(r[1]), "=r"(r[2]), "=r"(r[3]) : "r"(addr));
}
__device__ __forceinline__ void ldsm4t(uint32_t r[4], uint32_t addr) {
    asm volatile("ldmatrix.sync.aligned.m8n8.x4.trans.shared.b16 {%0,%1,%2,%3}, [%4];"
                 : "=r"(r[0]), "=r"(r[1]), "=r"(r[2]), "=r"(r[3]) : "r"(addr));
}
__device__ __forceinline__ void mma16816(float d[4], const uint32_t a[4],
                                         uint32_t b0, uint32_t b1) {
    asm volatile("mma.sync.aligned.m16n8k16.row.col.f32.bf16.bf16.f32 "
                 "{%0,%1,%2,%3}, {%4,%5,%6,%7}, {%8,%9}, {%0,%1,%2,%3};"
                 : "+f"(d[0]), "+f"(d[1]), "+f"(d[2]), "+f"(d[3])
                 : "r"(a[0]), "r"(a[1]), "r"(a[2]), "r"(a[3]),
                   "r"(b0), "r"(b1));
}
__device__ __forceinline__ void bulk_ld(uint32_t dst, const void* src,
                                        uint32_t bytes, uint32_t mbar) {
    asm volatile("cp.async.bulk.shared::cluster.global.mbarrier::complete_tx::bytes "
                 "[%0], [%1], %2, [%3];"
                 :: "r"(dst), "l"(src), "r"(bytes), "r"(mbar) : "memory");
}
__device__ __forceinline__ void mbar_init(uint32_t a, uint32_t cnt) {
    asm volatile("mbarrier.init.shared.b64 [%0], %1;" :: "r"(a), "r"(cnt) : "memory");
}
__device__ __forceinline__ void mbar_expect_tx(uint32_t a, uint32_t bytes) {
    asm volatile("mbarrier.arrive.expect_tx.shared.b64 _, [%0], %1;"
                 :: "r"(a), "r"(bytes) : "memory");
}
__device__ __forceinline__ void mbar_wait(uint32_t a, uint32_t parity) {
    asm volatile(
        "{\n\t.reg .pred P;\n\t"
        "WAIT_%=:\n\t"
        "mbarrier.try_wait.parity.acquire.cta.shared::cta.b64 P, [%0], %1, 0x989680;\n\t"
        "@P bra.uni DONE_%=;\n\t"
        "bra.uni WAIT_%=;\n\t"
        "DONE_%=:\n\t}"
        :: "r"(a), "r"(parity) : "memory");
}
__device__ __forceinline__ void fence_async_init() {
    asm volatile("fence.proxy.async.shared::cta;" ::: "memory");
}

__device__ __forceinline__ void bf16split(float x, __nv_bfloat16& h, __nv_bfloat16& l) {
    h = __float2bfloat16(x);
    l = __float2bfloat16(x - __bfloat162float(h));
}
__device__ __forceinline__ void split2pack(float a, float b, uint32_t& hp, uint32_t& lp) {
    __nv_bfloat16 ha, la, hb, lb;
    bf16split(a, ha, la);
    bf16split(b, hb, lb);
    __nv_bfloat162 h; h.x = ha; h.y = hb;
    __nv_bfloat162 l; l.x = la; l.y = lb;
    hp = *(uint32_t*)&h;
    lp = *(uint32_t*)&l;
}

// ---------------------------------------------------------------------------
// Convert X into tiled, pre-swizzled bf16 hi/lo tile pairs (1MB read)
// ---------------------------------------------------------------------------
__global__ __launch_bounds__(256) void conv_x_kernel(const float4* __restrict__ X) {
    uint32_t gid = blockIdx.x * 256 + threadIdx.x;
    float4 v = X[gid];
    uint32_t r = gid >> 10;
    uint32_t c = (gid & 1023) * 4;
    char* base = g_Xt + (size_t)(c >> 6) * TILEP;
    const uint32_t i = r & 63, j = c & 63;
    const uint32_t sw = (i * 128 + j * 2) ^ ((i & 7) << 4);
    uint32_t h0, l0, h1, l1;
    split2pack(v.x, v.y, h0, l0);
    split2pack(v.z, v.w, h1, l1);
    *(uint2*)(base + sw)        = make_uint2(h0, h1);
    *(uint2*)(base + 8192 + sw) = make_uint2(l0, l1);
}

// ---------------------------------------------------------------------------
// Zero-init Y and Z (outputs accumulated via atomicAdd each replay)
// ---------------------------------------------------------------------------
__global__ __launch_bounds__(256) void zero_kernel(float* __restrict__ a,
                                                   float* __restrict__ b) {
    int i = blockIdx.x * 256 + threadIdx.x;
    a[i] = 0.0f;
    b[i] = 0.0f;
}

// ---------------------------------------------------------------------------
// G~ = 2 * (F^T F) / (||F^T F||_F + 1e-12) - I
// ---------------------------------------------------------------------------
__global__ __launch_bounds__(256) void prep_kernel(const float* __restrict__ F) {
    __shared__ float Fs[MDIM][MDIM + 1];
    __shared__ float FFs[MDIM][MDIM + 4];
    __shared__ float red[8];
    __shared__ float s_inv;

    int t = threadIdx.x;
    for (int o = t; o < MDIM * MDIM; o += 256)
        Fs[o >> 6][o & 63] = F[o];
    __syncthreads();

    int i  = t >> 2;
    int j0 = (t & 3) * 16;
    float acc[16];
#pragma unroll
    for (int u = 0; u < 16; u++) acc[u] = 0.0f;
    for (int k = 0; k < MDIM; k++) {
        float a = Fs[k][i];
#pragma unroll
        for (int u = 0; u < 16; u++) acc[u] = fmaf(a, Fs[k][j0 + u], acc[u]);
    }
    float ss = 0.0f;
#pragma unroll
    for (int u = 0; u < 16; u++) {
        FFs[i][j0 + u] = acc[u];
        ss = fmaf(acc[u], acc[u], ss);
    }
#pragma unroll
    for (int off = 16; off > 0; off >>= 1)
        ss += __shfl_xor_sync(0xffffffffu, ss, off);
    if ((t & 31) == 0) red[t >> 5] = ss;
    __syncthreads();
    if (t == 0) {
        float tot = 0.0f;
        for (int w = 0; w < 8; w++) tot += red[w];
        s_inv = 2.0f / (sqrtf(tot) + 1e-12f);
    }
    __syncthreads();
    float inv = s_inv;
#pragma unroll
    for (int u = 0; u < 16; u++) {
        int j = j0 + u;
        g_Gt[i * MDIM + j] = FFs[i][j] * inv - (i == j ? 1.0f : 0.0f);
    }
}

// ---------------------------------------------------------------------------
// bf16 tensor GEMM. A tiles: pre-converted pairs, ONE 16KB TMA bulk per chunk.
// B tiles: fp32 loaded from Q via registers (4x LDG.128/thread, 2-chunk
// prefetch), split to bf16 hi/lo in registers, stored to a double-buffered
// swizzled pair. No small TMA requests; no empty barriers (syncthreads).
// TRANSB=0: B = Q[k, jg..]; TRANSB=1: B = Q[jg.., k]
// ---------------------------------------------------------------------------
template <int TRANSB>
__global__ __launch_bounds__(256) void gemm_bf(const char* __restrict__ At,
                                               const float* __restrict__ Q,
                                               float* __restrict__ C) {
    extern __shared__ __align__(128) char sm[];
    const uint32_t smb = sptr(sm);

    const int t    = threadIdx.x;
    const int lane = t & 31;
    const int warp = t >> 5;
    const int jb   = blockIdx.x;
    const int jg   = jb * BN;
    const int kb0  = blockIdx.y * (KSPL / 64);
    const int mw   = (warp & 3) * 16;
    const int nw   = (warp >> 2) * 32;
    const int lr   = lane & 15;
    const int g8   = (lane >> 4) * 8;

    if (t == 0) {
#pragma unroll
        for (int s = 0; s < NST; s++)
            mbar_init(smb + s * 16, 1);
        fence_async_init();
    }
    __syncthreads();

    const char* srcA = At + (size_t)kb0 * TILEP;
    const uint32_t stage0 = smb + 128;
    const uint32_t pair0  = smb + 128 + NST * ATILE;

    // B register-load role: thread t -> tile row r = t>>2, col quarter (t&3)*16
    const int br = t >> 2;
    const int bc = (t & 3) * 16;
    const float* srcB;
    long dBf;   // float advance per chunk
    if (TRANSB) { srcB = Q + (size_t)(jg + br) * NDIM + (size_t)kb0 * 64 + bc; dBf = 64; }
    else        { srcB = Q + ((size_t)kb0 * 64 + br) * NDIM + jg + bc;         dBf = (long)64 * NDIM; }

    // convert store offsets (2 x 16B groups per half)
    const uint32_t cvx = ((uint32_t)br & 7) << 4;
    const uint32_t cv0 = ((uint32_t)br * 128 + (uint32_t)bc * 2)      ^ cvx;
    const uint32_t cv1 = ((uint32_t)br * 128 + (uint32_t)bc * 2 + 16) ^ cvx;

    // ldsm offsets
    const uint32_t xorv = (uint32_t)(lane & 7) << 4;
    uint32_t aoffs[4];
#pragma unroll
    for (int ks = 0; ks < 4; ks++)
        aoffs[ks] = (uint32_t)(mw + lr) * 128 + (((uint32_t)(ks * 32 + g8 * 2)) ^ xorv);
    uint32_t boffs[4][2];
#pragma unroll
    for (int ks = 0; ks < 4; ks++)
#pragma unroll
        for (int half = 0; half < 2; half++) {
            if (TRANSB == 0)
                boffs[ks][half] = (uint32_t)(ks * 16 + lr) * 128 +
                                  (((uint32_t)((nw + half * 16 + g8) * 2)) ^ xorv);
            else
                boffs[ks][half] = (uint32_t)(nw + half * 16 + lr) * 128 +
                                  (((uint32_t)(ks * 32 + g8 * 2)) ^ xorv);
        }

    float acc[4][4];
#pragma unroll
    for (int nt = 0; nt < 4; nt++)
#pragma unroll
        for (int u = 0; u < 4; u++) acc[nt][u] = 0.0f;

    float rb[2][16];

    // prologue: A bulks for chunks 0,1; B regs for chunks 0,1
    if (t == 0) {
#pragma unroll
        for (int cn = 0; cn < 2; cn++) {
            const uint32_t full = smb + cn * 16;
            mbar_expect_tx(full, ATX);
            bulk_ld(stage0 + cn * ATILE, srcA + (long)cn * TILEP, ATILE, full);
        }
    }
#pragma unroll
    for (int p = 0; p < 2; p++) {
        const float* s0 = srcB + (long)p * dBf;
#pragma unroll
        for (int qf = 0; qf < 4; qf++)
            *(float4*)&rb[p][4 * qf] = *(const float4*)(s0 + 4 * qf);
    }

#pragma unroll
    for (int cb = 0; cb < NCH; cb += NST) {
        const int q    = cb / NST;
        const int cpar = q & 1;
#pragma unroll
        for (int s = 0; s < NST; s++) {
            const int cc = cb + s;
            if (cc >= NCH) break;
            const int cn = cc + 2;

            mbar_wait(smb + s * 16, cpar);     // A of chunk cc ready
            __syncthreads();                   // all threads done with chunk cc-1

            if (cn < NCH && t == 0) {
                const int s2 = cn % NST;
                const uint32_t full = smb + s2 * 16;
                mbar_expect_tx(full, ATX);
                bulk_ld(stage0 + s2 * ATILE, srcA + (long)cn * TILEP, ATILE, full);
            }

            // convert rb[cc&1] -> pair[cc&1]
            {
                const uint32_t P = pair0 + (uint32_t)(cc & 1) * TILEP;
                uint32_t hp[8], lp[8];
#pragma unroll
                for (int u = 0; u < 8; u++)
                    split2pack(rb[cc & 1][2 * u], rb[cc & 1][2 * u + 1], hp[u], lp[u]);
                asm volatile("st.shared.v4.b32 [%0], {%1,%2,%3,%4};"
                             :: "r"(P + cv0), "r"(hp[0]), "r"(hp[1]), "r"(hp[2]), "r"(hp[3]));
                asm volatile("st.shared.v4.b32 [%0], {%1,%2,%3,%4};"
                             :: "r"(P + cv1), "r"(hp[4]), "r"(hp[5]), "r"(hp[6]), "r"(hp[7]));
                asm volatile("st.shared.v4.b32 [%0], {%1,%2,%3,%4};"
                             :: "r"(P + 8192 + cv0), "r"(lp[0]), "r"(lp[1]), "r"(lp[2]), "r"(lp[3]));
                asm volatile("st.shared.v4.b32 [%0], {%1,%2,%3,%4};"
                             :: "r"(P + 8192 + cv1), "r"(lp[4]), "r"(lp[5]), "r"(lp[6]), "r"(lp[7]));
            }

            // prefetch B regs for chunk cn (reuses buffer just consumed)
            if (cn < NCH) {
                const float* s0 = srcB + (long)cn * dBf;
#pragma unroll
                for (int qf = 0; qf < 4; qf++)
                    *(float4*)&rb[cc & 1][4 * qf] = *(const float4*)(s0 + 4 * qf);
            }

            __syncthreads();                   // pair visible to all warps

            const uint32_t Ah = stage0 + s * ATILE;
            const uint32_t Al = Ah + 8192;
            const uint32_t Bh = pair0 + (uint32_t)(cc & 1) * TILEP;
            const uint32_t Bl = Bh + 8192;

#pragma unroll
            for (int ks = 0; ks < 4; ks++) {
                uint32_t ah[4], al[4];
                ldsm4(ah, Ah + aoffs[ks]);
                ldsm4(al, Al + aoffs[ks]);
#pragma unroll
                for (int half = 0; half < 2; half++) {
                    uint32_t bh[4], bl[4];
                    if (TRANSB == 0) {
                        ldsm4t(bh, Bh + boffs[ks][half]);
                        ldsm4t(bl, Bl + boffs[ks][half]);
                        mma16816(acc[half * 2],     ah, bh[0], bh[1]);
                        mma16816(acc[half * 2],     ah, bl[0], bl[1]);
                        mma16816(acc[half * 2],     al, bh[0], bh[1]);
                        mma16816(acc[half * 2 + 1], ah, bh[2], bh[3]);
                        mma16816(acc[half * 2 + 1], ah, bl[2], bl[3]);
                        mma16816(acc[half * 2 + 1], al, bh[2], bh[3]);
                    } else {
                        ldsm4(bh, Bh + boffs[ks][half]);
                        ldsm4(bl, Bl + boffs[ks][half]);
                        mma16816(acc[half * 2],     ah, bh[0], bh[2]);
                        mma16816(acc[half * 2],     ah, bl[0], bl[2]);
                        mma16816(acc[half * 2],     al, bh[0], bh[2]);
                        mma16816(acc[half * 2 + 1], ah, bh[1], bh[3]);
                        mma16816(acc[half * 2 + 1], ah, bl[1], bl[3]);
                        mma16816(acc[half * 2 + 1], al, bh[1], bh[3]);
                    }
                }
            }
        }
    }

    const int row = mw + (lane >> 2);
#pragma unroll
    for (int nt = 0; nt < 4; nt++) {
        const int col = jg + nw + (nt >> 1) * 16 + (nt & 1) * 8 + (lane & 3) * 2;
        atomicAdd(&C[(size_t)row * NDIM + col],           acc[nt][0]);
        atomicAdd(&C[(size_t)row * NDIM + col + 1],       acc[nt][1]);
        atomicAdd(&C[(size_t)(row + 8) * NDIM + col],     acc[nt][2]);
        atomicAdd(&C[(size_t)(row + 8) * NDIM + col + 1], acc[nt][3]);
    }
}

// ---------------------------------------------------------------------------
// Tensor-core Chebyshev (unchanged). Output into tiled/pre-swizzled g_Ztt.
// ---------------------------------------------------------------------------
__global__ __launch_bounds__(256) void cheb_tc(const float* __restrict__ lamS,
                                               const float* __restrict__ gammap) {
    extern __shared__ __align__(16) __nv_bfloat16 cs[];
    __nv_bfloat16* Gh = cs;
    __nv_bfloat16* Gl = cs + 64 * GST;
    __nv_bfloat16* Tbh = cs + 2 * 64 * GST;
    __nv_bfloat16* Tbl = Tbh + 3 * 64 * TST;
    __shared__ float sh_base[32];
    __shared__ float sh_r[32];

    const int t    = threadIdx.x;
    const int lane = t & 31;
    const int warp = t >> 5;
    const int jg   = blockIdx.x * 32;
    const int mw   = (warp & 3) * 16;
    const int nw   = (warp >> 2) * 16;
    const int lr   = lane & 15;
    const int g8   = (lane >> 4) * 8;

    for (int o = t; o < MDIM * MDIM; o += 256) {
        int r = o >> 6, c = o & 63;
        __nv_bfloat16 h, l;
        bf16split(g_Gt[o], h, l);
        Gh[r * GST + c] = h;
        Gl[r * GST + c] = l;
    }
    for (int o = t; o < MDIM * 32; o += 256) {
        int r = o >> 5, c = o & 31;
        __nv_bfloat16 h, l;
        bf16split(g_Y[(size_t)r * NDIM + jg + c], h, l);
        Tbh[r * TST + c] = h;
        Tbl[r * TST + c] = l;
    }
    if (t < 32) {
        float gam = gammap[0];
        float a = gam * lamS[jg + t];
        float base, r;
        if (fabsf(a) < 1e-7f) {
            base = 1.0f; r = 0.0f;
        } else {
            float b  = 2.0f / a - 1.0f;
            float ab = fabsf(b);
            float s  = sqrtf(fmaf(ab, ab, -1.0f));
            float q  = 1.0f / (ab + s);
            float sg = (a > 0.0f) ? 1.0f : -1.0f;
            r    = sg * q;
            base = (2.0f / a) * sg * 2.0f * q / (1.0f - q * q);
        }
        sh_base[t] = base;
        sh_r[t]    = r;
    }
    __syncthreads();

    uint32_t gh[4][4], gl[4][4];
#pragma unroll
    for (int ks = 0; ks < 4; ks++) {
        ldsm4(gh[ks], sptr(Gh + (mw + lr) * GST + ks * 16 + g8));
        ldsm4(gl[ks], sptr(Gl + (mw + lr) * GST + ks * 16 + g8));
    }

    const int row0 = mw + (lane >> 2);
    float basev[2][2], rv[2][2], pv[2][2];
#pragma unroll
    for (int nt = 0; nt < 2; nt++) {
        int c0 = nw + nt * 8 + 2 * (lane & 3);
        basev[nt][0] = sh_base[c0];     basev[nt][1] = sh_base[c0 + 1];
        rv[nt][0]    = sh_r[c0];        rv[nt][1]    = sh_r[c0 + 1];
        pv[nt][0] = 2.0f * basev[nt][0] * rv[nt][0];
        pv[nt][1] = 2.0f * basev[nt][1] * rv[nt][1];
    }

    float acc[2][4], prev[2][4], tp[2][4];
#pragma unroll
    for (int nt = 0; nt < 2; nt++) {
        int c0 = nw + nt * 8 + 2 * (lane & 3);
        float2 y0 = *(const float2*)&g_Y[(size_t)row0 * NDIM + jg + c0];
        float2 y1 = *(const float2*)&g_Y[(size_t)(row0 + 8) * NDIM + jg + c0];
        prev[nt][0] = y0.x; prev[nt][1] = y0.y; prev[nt][2] = y1.x; prev[nt][3] = y1.y;
        acc[nt][0] = basev[nt][0] * y0.x;
        acc[nt][1] = basev[nt][1] * y0.y;
        acc[nt][2] = basev[nt][0] * y1.x;
        acc[nt][3] = basev[nt][1] * y1.y;
        tp[nt][0] = tp[nt][1] = tp[nt][2] = tp[nt][3] = 0.0f;
    }

    for (int k = 1; k < KCHEB; k++) {
        __syncthreads();
        const __nv_bfloat16* Th = Tbh + ((k - 1) % 3) * (64 * TST);
        const __nv_bfloat16* Tl = Tbl + ((k - 1) % 3) * (64 * TST);
        float u[2][4];
#pragma unroll
        for (int nt = 0; nt < 2; nt++)
#pragma unroll
            for (int i = 0; i < 4; i++) u[nt][i] = 0.0f;
#pragma unroll
        for (int ks = 0; ks < 4; ks++) {
            uint32_t th[4], tl[4];
            ldsm4t(th, sptr(Th + (ks * 16 + lr) * TST + nw + g8));
            ldsm4t(tl, sptr(Tl + (ks * 16 + lr) * TST + nw + g8));
            mma16816(u[0], gh[ks], th[0], th[1]);
            mma16816(u[0], gh[ks], tl[0], tl[1]);
            mma16816(u[0], gl[ks], th[0], th[1]);
            mma16816(u[1], gh[ks], th[2], th[3]);
            mma16816(u[1], gh[ks], tl[2], tl[3]);
            mma16816(u[1], gl[ks], th[2], th[3]);
        }
        float tn[2][4];
#pragma unroll
        for (int nt = 0; nt < 2; nt++)
#pragma unroll
            for (int i = 0; i < 4; i++)
                tn[nt][i] = (k == 1) ? u[nt][i] : fmaf(2.0f, u[nt][i], -tp[nt][i]);
#pragma unroll
        for (int nt = 0; nt < 2; nt++) {
            acc[nt][0] = fmaf(pv[nt][0], tn[nt][0], acc[nt][0]);
            acc[nt][1] = fmaf(pv[nt][1], tn[nt][1], acc[nt][1]);
            acc[nt][2] = fmaf(pv[nt][0], tn[nt][2], acc[nt][2]);
            acc[nt][3] = fmaf(pv[nt][1], tn[nt][3], acc[nt][3]);
            pv[nt][0] *= rv[nt][0];
            pv[nt][1] *= rv[nt][1];
        }
        if (k < KCHEB - 1) {
            __nv_bfloat16* Wh = Tbh + (k % 3) * (64 * TST);
            __nv_bfloat16* Wl = Tbl + (k % 3) * (64 * TST);
#pragma unroll
            for (int nt = 0; nt < 2; nt++) {
                int c0 = nw + nt * 8 + 2 * (lane & 3);
                uint32_t hp, lp;
                split2pack(tn[nt][0], tn[nt][1], hp, lp);
                *(uint32_t*)(Wh + row0 * TST + c0) = hp;
                *(uint32_t*)(Wl + row0 * TST + c0) = lp;
                split2pack(tn[nt][2], tn[nt][3], hp, lp);
                *(uint32_t*)(Wh + (row0 + 8) * TST + c0) = hp;
                *(uint32_t*)(Wl + (row0 + 8) * TST + c0) = lp;
            }
        }
#pragma unroll
        for (int nt = 0; nt < 2; nt++)
#pragma unroll
            for (int i = 0; i < 4; i++) {
                tp[nt][i]   = prev[nt][i];
                prev[nt][i] = tn[nt][i];
            }
    }

    {
        char* Zt = g_Ztt + (size_t)(jg >> 6) * TILEP;
        const uint32_t jo = jg & 63;
#pragma unroll
        for (int nt = 0; nt < 2; nt++) {
            const uint32_t c0 = nw + nt * 8 + 2 * (lane & 3);
            uint32_t hp, lp;
            split2pack(acc[nt][0], acc[nt][1], hp, lp);
            uint32_t o0 = (uint32_t)row0 * 128 + (((jo + c0) * 2) ^ (((uint32_t)row0 & 7) << 4));
            *(uint32_t*)(Zt + o0)        = hp;
            *(uint32_t*)(Zt + 8192 + o0) = lp;
            split2pack(acc[nt][2], acc[nt][3], hp, lp);
            uint32_t o1 = (uint32_t)(row0 + 8) * 128 + (((jo + c0) * 2) ^ (((uint32_t)row0 & 7) << 4));
            *(uint32_t*)(Zt + o1)        = hp;
            *(uint32_t*)(Zt + 8192 + o1) = lp;
        }
    }
}

#define CHEB_SMEM ((2 * 64 * GST + 6 * 64 * TST) * 2)

// ---------------------------------------------------------------------------
extern "C" void kernel_launch(void* const* d_in, const int* in_sizes, int n_in,
                              void* d_out, int out_size) {
    const float* X    = (const float*)d_in[0];   // (64, 4096)
    const float* F    = (const float*)d_in[1];   // (64, 64)
    const float* Q_S  = (const float*)d_in[2];   // (4096, 4096)
    const float* lamS = (const float*)d_in[3];   // (4096,)
    const float* gam  = (const float*)d_in[4];   // scalar
    float* Z = (float*)d_out;                    // (64, 4096)

    float* Y;
    char *Xt, *Ztt;
    cudaGetSymbolAddress((void**)&Y,   g_Y);
    cudaGetSymbolAddress((void**)&Xt,  g_Xt);
    cudaGetSymbolAddress((void**)&Ztt, g_Ztt);

    static bool attr_set = false;
    if (!attr_set) {
        cudaFuncSetAttribute(gemm_bf<0>, cudaFuncAttributeMaxDynamicSharedMemorySize, GEMM_SMEM);
        cudaFuncSetAttribute(gemm_bf<1>, cudaFuncAttributeMaxDynamicSharedMemorySize, GEMM_SMEM);
        cudaFuncSetAttribute(cheb_tc,    cudaFuncAttributeMaxDynamicSharedMemorySize, CHEB_SMEM);
        attr_set = true;
    }

    dim3 ggrid(NDIM / BN, NSPLIT);

    conv_x_kernel<<<(MDIM * NDIM / 4) / 256, 256>>>((const float4*)X);
    zero_kernel<<<(MDIM * NDIM) / 256, 256>>>(Y, Z);
    prep_kernel<<<1, 256>>>(F);
    gemm_bf<0><<<ggrid, 256, GEMM_SMEM>>>(Xt, Q_S, Y);    // Y += X @ Q_S
    cheb_tc<<<NDIM / 32, 256, CHEB_SMEM>>>(lamS, gam);    // Ztt = f(G) Y (tiled)
    gemm_bf<1><<<ggrid, 256, GEMM_SMEM>>>(Ztt, Q_S, Z);   // Z += Z~ @ Q_S^T
}